// round 4
// baseline (speedup 1.0000x reference)
#include <cuda_runtime.h>

#define NROW 8
#define ROWN (1 << 20)          // elements per batch row
#define N4   (ROWN / 4)         // float4 count per row
#define NBIN 2048
#define NCOPY 2                 // shared-hist copies (warp parity)
#define BPR  37                 // blocks per row (296 total ~ 2/SM, single wave)
#define TPB  256
#define K_ALL 524288.0f         // max(1, int(N * 0.5))
#define SUMSCALE 4194304.0f     // 2^22 fixed-point scale for packed sums
#define INV_SUMSCALE 2.384185791015625e-7f   // 2^-22
#define CNT_SHIFT 44
#define SUM_MASK ((1ull << CNT_SHIFT) - 1ull)

// ---- global scratch (zero-initialized at load; tail restores zeros) ----
__device__ unsigned long long g_hist[NROW][NBIN];
__device__ float    g_sum_pos[NROW];
__device__ unsigned g_n_pos[NROW];
__device__ unsigned g_row_done[NROW];
__device__ float    g_per[NROW];
__device__ unsigned g_done;

// ---------------------------------------------------------------
// Single fused kernel: BCE + hist build; per-row last block selects.
// grid = (BPR, NROW), block = TPB
// ---------------------------------------------------------------
__global__ __launch_bounds__(TPB) void ohem_fused(
    const float* __restrict__ logits,
    const int*   __restrict__ targets,
    const int*   __restrict__ mask,
    float*       __restrict__ d_out)
{
    __shared__ unsigned long long s_hist[NCOPY][NBIN];
    __shared__ float    r_sp[TPB / 32];
    __shared__ unsigned r_np[TPB / 32];
    __shared__ unsigned s_wc[TPB / 32], s_wca[TPB / 32];
    __shared__ float    s_wf[TPB / 32], s_wfa[TPB / 32];
    __shared__ float    sh_kept;
    __shared__ unsigned sh_nneg;
    __shared__ int      sh_last;

    const int row  = blockIdx.y;
    const int tid  = threadIdx.x;
    const int lane = tid & 31;
    const int wid  = tid >> 5;

    {
        unsigned long long* p = &s_hist[0][0];
        #pragma unroll
        for (int i = tid; i < NCOPY * NBIN; i += TPB) p[i] = 0ull;
    }
    __syncthreads();

    unsigned long long* myh = s_hist[wid & (NCOPY - 1)];

    const float4* xl = (const float4*)(logits  + (size_t)row * ROWN);
    const int4*   tl = (const int4*)  (targets + (size_t)row * ROWN);
    const int4*   ml = (const int4*)  (mask    + (size_t)row * ROWN);

    float    sp = 0.f;
    unsigned np = 0u;

    const int stride = BPR * TPB;

    #pragma unroll 4
    for (int i = blockIdx.x * TPB + tid; i < N4; i += stride) {
        float4 x4 = xl[i];
        int4   t4 = tl[i];
        int4   m4 = ml[i];

        float xs[4] = {x4.x, x4.y, x4.z, x4.w};
        int   ts[4] = {t4.x, t4.y, t4.z, t4.w};
        int   ms[4] = {m4.x, m4.y, m4.z, m4.w};

        #pragma unroll
        for (int k = 0; k < 4; k++) {
            float x = xs[k];
            // stable BCE-with-logits: max(x,0) - x*t + log1p(exp(-|x|))
            float bce = fmaxf(x, 0.f) - x * (float)ts[k]
                      + __logf(1.f + __expf(-fabsf(x)));
            bce = fmaxf(bce, 0.f);
            if (ms[k]) {
                if (ts[k]) {
                    sp += bce; np++;
                } else {
                    unsigned bin = __float_as_uint(bce) >> 21;  // < 2048
                    unsigned long long pk = (1ull << CNT_SHIFT)
                        + (unsigned long long)(bce * SUMSCALE + 0.5f);
                    atomicAdd(&myh[bin], pk);
                }
            }
        }
    }

    // reduce positives
    #pragma unroll
    for (int o = 16; o > 0; o >>= 1) {
        sp += __shfl_down_sync(0xffffffffu, sp, o);
        np += __shfl_down_sync(0xffffffffu, np, o);
    }
    if (lane == 0) { r_sp[wid] = sp; r_np[wid] = np; }
    __syncthreads();

    if (tid == 0) {
        float bsp = 0.f; unsigned bnp = 0u;
        #pragma unroll
        for (int w = 0; w < TPB / 32; w++) { bsp += r_sp[w]; bnp += r_np[w]; }
        atomicAdd(&g_sum_pos[row], bsp);
        atomicAdd(&g_n_pos[row],   bnp);
    }

    // flush merged copies (sparse: ~30-60 hot bins)
    for (int b = tid; b < NBIN; b += TPB) {
        unsigned long long v = s_hist[0][b] + s_hist[1][b];
        if (v) atomicAdd(&g_hist[row][b], v);
    }

    __threadfence();
    if (tid == 0) {
        unsigned old = atomicAdd(&g_row_done[row], 1u);
        sh_last = (old == BPR - 1) ? 1 : 0;
    }
    __syncthreads();
    if (!sh_last) return;

    // ============ per-row selection (last block of this row) ============
    __threadfence();   // acquire: see all other blocks' hist/accumulator writes

    const float fnpos  = (float)g_n_pos[row];
    const float sp_row = g_sum_pos[row];

    unsigned cnt8[8];
    float    sum8[8];
    unsigned csum = 0u;
    float    fsum = 0.f;
    #pragma unroll
    for (int k = 0; k < 8; k++) {
        unsigned long long v = g_hist[row][tid * 8 + k];
        cnt8[k] = (unsigned)(v >> CNT_SHIFT);
        sum8[k] = (float)(v & SUM_MASK) * INV_SUMSCALE;
        csum += cnt8[k];
        fsum += sum8[k];
    }

    // intra-warp inclusive suffix scan (lane i gets sum over lanes i..31)
    unsigned ci = csum; float fi = fsum;
    #pragma unroll
    for (int off = 1; off < 32; off <<= 1) {
        unsigned c2 = __shfl_down_sync(0xffffffffu, ci, off);
        float    f2 = __shfl_down_sync(0xffffffffu, fi, off);
        if (lane + off < 32) { ci += c2; fi += f2; }
    }
    if (lane == 0) { s_wc[wid] = ci; s_wf[wid] = fi; }
    if (tid == 0) sh_kept = 0.f;
    __syncthreads();

    if (tid == 0) {   // tiny 8-entry suffix-exclusive over warp totals
        unsigned ca = 0u; float sa = 0.f;
        for (int w = (TPB / 32) - 1; w >= 0; w--) {
            s_wca[w] = ca; s_wfa[w] = sa;
            ca += s_wc[w]; sa += s_wf[w];
        }
        sh_nneg = ca;
    }
    __syncthreads();

    const float fnneg = (float)sh_nneg;
    const float jf    = fminf(fmaxf(K_ALL - fnpos, 0.f), fnneg);
    const unsigned ju = (unsigned)jf;

    if (ju > 0u) {
        // exclusive "strictly above this thread's chunk"
        unsigned ca = s_wca[wid] + (ci - csum);
        float    sa = s_wfa[wid] + (fi - fsum);
        #pragma unroll
        for (int k = 7; k >= 0; k--) {   // walk bins high -> low
            unsigned c = cnt8[k];
            if (c && ca < ju && ca + c >= ju) {
                float r    = (float)(ju - ca);
                float mean = sum8[k] / (float)c;
                sh_kept = sa + r * mean;     // exactly one thread matches
            }
            ca += c;
            sa += sum8[k];
        }
    }

    // cleanup for next graph replay (all reads of this row's globals done)
    #pragma unroll
    for (int k = 0; k < 8; k++) g_hist[row][tid * 8 + k] = 0ull;
    if (tid == 0) {
        g_sum_pos[row]  = 0.f;
        g_n_pos[row]    = 0u;
        g_row_done[row] = 0u;
    }
    __syncthreads();

    if (tid == 0) {
        float kkeep = fnpos + jf;
        float ps = (kkeep > 0.f)
                 ? (sp_row + sh_kept) / fmaxf(kkeep, 1.f)
                 : 0.f;
        g_per[row] = ps;
        __threadfence();
        unsigned old = atomicAdd(&g_done, 1u);
        if (old == NROW - 1) {
            __threadfence();
            g_done = 0u;                  // reset for next replay
            volatile float* vp = g_per;
            float tot = 0.f;
            #pragma unroll
            for (int r = 0; r < NROW; r++) tot += vp[r];
            d_out[0] = tot * (1.f / (float)NROW);
        }
    }
}

// ---------------------------------------------------------------
extern "C" void kernel_launch(void* const* d_in, const int* in_sizes, int n_in,
                              void* d_out, int out_size)
{
    (void)in_sizes; (void)n_in; (void)out_size;
    const float* logits  = (const float*)d_in[0];
    const int*   targets = (const int*)d_in[1];
    const int*   mask    = (const int*)d_in[2];
    float*       out     = (float*)d_out;

    dim3 grid(BPR, NROW);
    ohem_fused<<<grid, TPB>>>(logits, targets, mask, out);
}

// round 6
// speedup vs baseline: 1.4366x; 1.4366x over previous
#include <cuda_runtime.h>

#define NROW 8
#define ROWN (1 << 20)          // elements per batch row
#define N4   (ROWN / 4)         // float4 count per row
#define NBIN 2048
#define NCOPY 2                 // shared-hist copies (warp parity)
#define BPR  74                 // blocks per row -> 592 blocks ~= 4/SM, 1 wave
#define TPB  256
#define K_ALL 524288.0f         // max(1, int(N * 0.5))
#define SUMSCALE 4194304.0f     // 2^22 fixed-point scale for packed sums
#define INV_SUMSCALE 2.384185791015625e-7f   // 2^-22
#define CNT_SHIFT 44
#define SUM_MASK ((1ull << CNT_SHIFT) - 1ull)

// ---- global scratch (zero-initialized at load; tail restores zeros) ----
__device__ unsigned long long g_hist[NROW][NBIN];
__device__ float    g_sum_pos[NROW];
__device__ unsigned g_n_pos[NROW];
__device__ unsigned g_row_done[NROW];
__device__ float    g_per[NROW];
__device__ unsigned g_done;

// ---------------------------------------------------------------
// Single fused kernel: BCE + hist build; per-row last block selects.
// grid = (BPR, NROW), block = TPB
// ---------------------------------------------------------------
__global__ __launch_bounds__(TPB, 4) void ohem_fused(
    const float* __restrict__ logits,
    const int*   __restrict__ targets,
    const int*   __restrict__ mask,
    float*       __restrict__ d_out)
{
    __shared__ unsigned long long s_hist[NCOPY][NBIN];
    __shared__ float    r_sp[TPB / 32];
    __shared__ unsigned r_np[TPB / 32];
    __shared__ unsigned s_wc[TPB / 32], s_wca[TPB / 32];
    __shared__ float    s_wf[TPB / 32], s_wfa[TPB / 32];
    __shared__ float    sh_kept;
    __shared__ unsigned sh_nneg;
    __shared__ int      sh_last;

    const int row  = blockIdx.y;
    const int tid  = threadIdx.x;
    const int lane = tid & 31;
    const int wid  = tid >> 5;

    {
        unsigned long long* p = &s_hist[0][0];
        #pragma unroll
        for (int i = tid; i < NCOPY * NBIN; i += TPB) p[i] = 0ull;
    }
    __syncthreads();

    unsigned long long* myh = s_hist[wid & (NCOPY - 1)];

    const float4* xl = (const float4*)(logits  + (size_t)row * ROWN);
    const int4*   tl = (const int4*)  (targets + (size_t)row * ROWN);
    const int4*   ml = (const int4*)  (mask    + (size_t)row * ROWN);

    float    sp = 0.f;
    unsigned np = 0u;

    const int stride = BPR * TPB;

    #pragma unroll 4
    for (int i = blockIdx.x * TPB + tid; i < N4; i += stride) {
        float4 x4 = xl[i];
        int4   t4 = tl[i];
        int4   m4 = ml[i];

        float xs[4] = {x4.x, x4.y, x4.z, x4.w};
        int   ts[4] = {t4.x, t4.y, t4.z, t4.w};
        int   ms[4] = {m4.x, m4.y, m4.z, m4.w};

        #pragma unroll
        for (int k = 0; k < 4; k++) {
            float x = xs[k];
            // stable BCE-with-logits: max(x,0) - x*t + log1p(exp(-|x|))
            float bce = fmaxf(x, 0.f) - x * (float)ts[k]
                      + __logf(1.f + __expf(-fabsf(x)));
            bce = fmaxf(bce, 0.f);
            if (ms[k]) {
                if (ts[k]) {
                    sp += bce; np++;
                } else {
                    unsigned bin = __float_as_uint(bce) >> 21;  // < 2048
                    unsigned long long pk = (1ull << CNT_SHIFT)
                        + (unsigned long long)(bce * SUMSCALE + 0.5f);
                    atomicAdd(&myh[bin], pk);
                }
            }
        }
    }

    // reduce positives
    #pragma unroll
    for (int o = 16; o > 0; o >>= 1) {
        sp += __shfl_down_sync(0xffffffffu, sp, o);
        np += __shfl_down_sync(0xffffffffu, np, o);
    }
    if (lane == 0) { r_sp[wid] = sp; r_np[wid] = np; }
    __syncthreads();

    if (tid == 0) {
        float bsp = 0.f; unsigned bnp = 0u;
        #pragma unroll
        for (int w = 0; w < TPB / 32; w++) { bsp += r_sp[w]; bnp += r_np[w]; }
        atomicAdd(&g_sum_pos[row], bsp);
        atomicAdd(&g_n_pos[row],   bnp);
    }

    // flush merged copies (sparse: ~30-60 hot bins)
    for (int b = tid; b < NBIN; b += TPB) {
        unsigned long long v = s_hist[0][b] + s_hist[1][b];
        if (v) atomicAdd(&g_hist[row][b], v);
    }

    __threadfence();
    if (tid == 0) {
        unsigned old = atomicAdd(&g_row_done[row], 1u);
        sh_last = (old == BPR - 1) ? 1 : 0;
    }
    __syncthreads();
    if (!sh_last) return;

    // ============ per-row selection (last block of this row) ============
    __threadfence();   // acquire: see all other blocks' hist/accumulator writes

    const float fnpos  = (float)g_n_pos[row];
    const float sp_row = g_sum_pos[row];

    unsigned cnt8[8];
    float    sum8[8];
    unsigned csum = 0u;
    float    fsum = 0.f;
    #pragma unroll
    for (int k = 0; k < 8; k++) {
        unsigned long long v = g_hist[row][tid * 8 + k];
        cnt8[k] = (unsigned)(v >> CNT_SHIFT);
        sum8[k] = (float)(v & SUM_MASK) * INV_SUMSCALE;
        csum += cnt8[k];
        fsum += sum8[k];
    }

    // intra-warp inclusive suffix scan (lane i gets sum over lanes i..31)
    unsigned ci = csum; float fi = fsum;
    #pragma unroll
    for (int off = 1; off < 32; off <<= 1) {
        unsigned c2 = __shfl_down_sync(0xffffffffu, ci, off);
        float    f2 = __shfl_down_sync(0xffffffffu, fi, off);
        if (lane + off < 32) { ci += c2; fi += f2; }
    }
    if (lane == 0) { s_wc[wid] = ci; s_wf[wid] = fi; }
    if (tid == 0) sh_kept = 0.f;
    __syncthreads();

    if (tid == 0) {   // tiny 8-entry suffix-exclusive over warp totals
        unsigned ca = 0u; float sa = 0.f;
        for (int w = (TPB / 32) - 1; w >= 0; w--) {
            s_wca[w] = ca; s_wfa[w] = sa;
            ca += s_wc[w]; sa += s_wf[w];
        }
        sh_nneg = ca;
    }
    __syncthreads();

    const float fnneg = (float)sh_nneg;
    const float jf    = fminf(fmaxf(K_ALL - fnpos, 0.f), fnneg);
    const unsigned ju = (unsigned)jf;

    if (ju > 0u) {
        // exclusive "strictly above this thread's chunk"
        unsigned ca = s_wca[wid] + (ci - csum);
        float    sa = s_wfa[wid] + (fi - fsum);
        #pragma unroll
        for (int k = 7; k >= 0; k--) {   // walk bins high -> low
            unsigned c = cnt8[k];
            if (c && ca < ju && ca + c >= ju) {
                float r    = (float)(ju - ca);
                float mean = sum8[k] / (float)c;
                sh_kept = sa + r * mean;     // exactly one thread matches
            }
            ca += c;
            sa += sum8[k];
        }
    }

    // cleanup for next graph replay (all reads of this row's globals done)
    #pragma unroll
    for (int k = 0; k < 8; k++) g_hist[row][tid * 8 + k] = 0ull;
    if (tid == 0) {
        g_sum_pos[row]  = 0.f;
        g_n_pos[row]    = 0u;
        g_row_done[row] = 0u;
    }
    __syncthreads();

    if (tid == 0) {
        float kkeep = fnpos + jf;
        float ps = (kkeep > 0.f)
                 ? (sp_row + sh_kept) / fmaxf(kkeep, 1.f)
                 : 0.f;
        g_per[row] = ps;
        __threadfence();
        unsigned old = atomicAdd(&g_done, 1u);
        if (old == NROW - 1) {
            __threadfence();
            g_done = 0u;                  // reset for next replay
            volatile float* vp = g_per;
            float tot = 0.f;
            #pragma unroll
            for (int r = 0; r < NROW; r++) tot += vp[r];
            d_out[0] = tot * (1.f / (float)NROW);
        }
    }
}

// ---------------------------------------------------------------
extern "C" void kernel_launch(void* const* d_in, const int* in_sizes, int n_in,
                              void* d_out, int out_size)
{
    (void)in_sizes; (void)n_in; (void)out_size;
    const float* logits  = (const float*)d_in[0];
    const int*   targets = (const int*)d_in[1];
    const int*   mask    = (const int*)d_in[2];
    float*       out     = (float*)d_out;

    dim3 grid(BPR, NROW);
    ohem_fused<<<grid, TPB>>>(logits, targets, mask, out);
}